// round 1
// baseline (speedup 1.0000x reference)
#include <cuda_runtime.h>
#include <cstdint>
#include <cstddef>

#define NQ   65536
#define MS   65536
#define HN   32
#define CIN  64
#define CO   64
#define KP   15

// ---- SMEM layout (dynamic) -------------------------------------------------
// [0, 123904)            : weighted tile  float wt[32][968]   (960 used, pad for banks)
// [123904, 123904+32768) : W chunk double buffer (2 x 4096 floats)
//                          -- aliased in phase A as per-lane influence table
//                             float ws[8 warps][32 lanes][16]
//                          -- aliased in epilogue as out_s[32][64]
// [156672, 156928)       : kernel points float4 kp4[16]
#define SMEM_WT_BYTES (32 * 968 * 4)
#define SMEM_WC_OFF   SMEM_WT_BYTES
#define SMEM_WC_BYTES (2 * 4096 * 4)
#define SMEM_KP_OFF   (SMEM_WC_OFF + SMEM_WC_BYTES)
#define SMEM_TOTAL    (SMEM_KP_OFF + 16 * 16)

// ---- BN scratch (device globals; no allocation allowed) ---------------------
__device__ float g_sums[CO];
__device__ float g_sumsq[CO];
__device__ float g_scale[CO];
__device__ float g_bias[CO];

// ---- packed fp32x2 helpers (FFMA2 only reachable via PTX) -------------------
static __device__ __forceinline__ unsigned long long pk2(float lo, float hi) {
    unsigned long long r;
    asm("mov.b64 %0, {%1, %2};" : "=l"(r) : "f"(lo), "f"(hi));
    return r;
}
static __device__ __forceinline__ void upk2(unsigned long long v, float &lo, float &hi) {
    asm("mov.b64 {%0, %1}, %2;" : "=f"(lo), "=f"(hi) : "l"(v));
}
static __device__ __forceinline__ unsigned long long ffma2(unsigned long long a,
                                                           unsigned long long b,
                                                           unsigned long long c) {
    unsigned long long d;
    asm("fma.rn.f32x2 %0, %1, %2, %3;" : "=l"(d) : "l"(a), "l"(b), "l"(c));
    return d;
}
static __device__ __forceinline__ float fast_sqrt(float x) {
    float r;
    asm("sqrt.approx.f32 %0, %1;" : "=f"(r) : "f"(x));
    return r;
}

// =============================================================================
// Kernel 0: zero BN accumulators (must run every launch: graph is replayed)
// =============================================================================
__global__ void zero_stats_kernel() {
    int t = threadIdx.x;
    if (t < CO) { g_sums[t] = 0.f; g_sumsq[t] = 0.f; }
}

// =============================================================================
// Kernel 1: fused KPConv (influence + aggregation + weight GEMM) + BN partials
// =============================================================================
extern __shared__ char smem_raw[];

__global__ void __launch_bounds__(256, 1)
kpconv_main(const float* __restrict__ x,
            const float* __restrict__ q_pts,
            const float* __restrict__ s_pts,
            const int*   __restrict__ nbr,
            const float* __restrict__ kp,
            const float* __restrict__ Wg,
            float*       __restrict__ out)
{
    float*  wt    = (float*)smem_raw;                    // [32][968]
    float*  wcbuf = (float*)(smem_raw + SMEM_WC_OFF);    // 8192 floats
    float4* kp4   = (float4*)(smem_raw + SMEM_KP_OFF);   // [16]
    float*  ws    = wcbuf;                               // phase-A alias [8][32][16]

    const int tid   = threadIdx.x;
    const int warp  = tid >> 5;
    const int lane  = tid & 31;
    const int qbase = blockIdx.x * 32;

    // preload kernel points
    if (tid < 16) {
        float4 v = make_float4(0.f, 0.f, 0.f, 0.f);
        if (tid < KP) {
            v.x = kp[tid * 3 + 0];
            v.y = kp[tid * 3 + 1];
            v.z = kp[tid * 3 + 2];
        }
        kp4[tid] = v;
    }
    __syncthreads();

    const double EXT_D = 0.1 * 1.2 / 2.5;
    const float  INV_E = (float)(1.0 / EXT_D);

    // ---------------- Phase A: warp-per-query influence + aggregation -------
    #pragma unroll 1
    for (int qi = 0; qi < 4; ++qi) {
        const int q = qbase + warp * 4 + qi;

        const float qx = q_pts[q * 3 + 0];
        const float qy = q_pts[q * 3 + 1];
        const float qz = q_pts[q * 3 + 2];

        const int idx = nbr[q * HN + lane];
        const float rx = s_pts[idx * 3 + 0] - qx;
        const float ry = s_pts[idx * 3 + 1] - qy;
        const float rz = s_pts[idx * 3 + 2] - qz;

        // per-lane (= per-neighbor) influence for all kernel points
        float* wrow = ws + (warp * 32 + lane) * 16;
        #pragma unroll
        for (int k = 0; k < 16; ++k) {
            float w = 0.f;
            if (k < KP) {
                float4 kv = kp4[k];
                float dx = rx - kv.x, dy = ry - kv.y, dz = rz - kv.z;
                float d2 = fmaf(dx, dx, fmaf(dy, dy, dz * dz));
                float s  = fast_sqrt(d2);
                w = fmaxf(fmaf(s, -INV_E, 1.f), 0.f);
            }
            wrow[k] = w;
        }
        __syncwarp();

        // accumulate weighted[k, i] ; lane owns i = {2*lane, 2*lane+1}
        // acc0[p] = {weighted[2p][i0], weighted[2p+1][i0]}  (k-paired f32x2)
        unsigned long long acc0[8], acc1[8];
        #pragma unroll
        for (int p = 0; p < 8; ++p) { acc0[p] = 0ULL; acc1[p] = 0ULL; }

        #pragma unroll 4
        for (int h = 0; h < HN; ++h) {
            const int ih = __shfl_sync(0xffffffffu, idx, h);
            const float2 xv = *(const float2*)(x + (size_t)ih * CIN + 2 * lane);
            const unsigned long long x0 = pk2(xv.x, xv.x);
            const unsigned long long x1 = pk2(xv.y, xv.y);
            const ulonglong2* wsv = (const ulonglong2*)(ws + (warp * 32 + h) * 16);
            #pragma unroll
            for (int pp = 0; pp < 4; ++pp) {
                ulonglong2 wv = wsv[pp];
                acc0[2 * pp]     = ffma2(wv.x, x0, acc0[2 * pp]);
                acc1[2 * pp]     = ffma2(wv.x, x1, acc1[2 * pp]);
                acc0[2 * pp + 1] = ffma2(wv.y, x0, acc0[2 * pp + 1]);
                acc1[2 * pp + 1] = ffma2(wv.y, x1, acc1[2 * pp + 1]);
            }
        }

        // spill weighted to SMEM tile: wt[qlocal][k*64 + i]
        float* wq = wt + (warp * 4 + qi) * 968;
        #pragma unroll
        for (int p = 0; p < 8; ++p) {
            float a0lo, a0hi, a1lo, a1hi;
            upk2(acc0[p], a0lo, a0hi);
            upk2(acc1[p], a1lo, a1hi);
            const int k0 = 2 * p, k1 = 2 * p + 1;
            *(float2*)(wq + k0 * 64 + 2 * lane) = make_float2(a0lo, a1lo);
            if (k1 < KP)
                *(float2*)(wq + k1 * 64 + 2 * lane) = make_float2(a0hi, a1hi);
        }
        __syncwarp();
    }
    __syncthreads();

    // ---------------- Phase B: out[32,64] = wt[32,960] x W[960,64] ----------
    const int q  = tid >> 3;
    const int oc = (tid & 7) * 8;
    float* wc0 = wcbuf;
    float* wc1 = wcbuf + 4096;
    const float4* Wg4 = (const float4*)Wg;   // 15 chunks x 1024 float4

    float4 pf[4];
    #pragma unroll
    for (int i = 0; i < 4; ++i) pf[i] = Wg4[tid + 256 * i];       // chunk 0
    #pragma unroll
    for (int i = 0; i < 4; ++i) ((float4*)wc0)[tid + 256 * i] = pf[i];
    __syncthreads();
    #pragma unroll
    for (int i = 0; i < 4; ++i) pf[i] = Wg4[1024 + tid + 256 * i]; // chunk 1

    unsigned long long acc[4] = {0ULL, 0ULL, 0ULL, 0ULL};
    const float* wtq = wt + q * 968;

    #pragma unroll 1
    for (int jc = 0; jc < 15; ++jc) {
        const float* wcc = (jc & 1) ? wc1 : wc0;
        const int jb = jc * 64;
        #pragma unroll 8
        for (int j = 0; j < 64; ++j) {
            const float a = wtq[jb + j];
            const unsigned long long a2 = pk2(a, a);
            const ulonglong2* wrow = (const ulonglong2*)(wcc + j * 64 + oc);
            const ulonglong2 w01 = wrow[0];
            const ulonglong2 w23 = wrow[1];
            acc[0] = ffma2(a2, w01.x, acc[0]);
            acc[1] = ffma2(a2, w01.y, acc[1]);
            acc[2] = ffma2(a2, w23.x, acc[2]);
            acc[3] = ffma2(a2, w23.y, acc[3]);
        }
        if (jc < 14) {
            float* wcn = (jc & 1) ? wc0 : wc1;
            __syncthreads();                       // everyone done with wcn
            #pragma unroll
            for (int i = 0; i < 4; ++i) ((float4*)wcn)[tid + 256 * i] = pf[i];
            if (jc < 13) {
                #pragma unroll
                for (int i = 0; i < 4; ++i)
                    pf[i] = Wg4[(jc + 2) * 1024 + tid + 256 * i];
            }
            __syncthreads();                       // wcn visible to all
        }
    }

    // ---------------- epilogue: write raw out + BN partial sums -------------
    float ov[8];
    #pragma unroll
    for (int i = 0; i < 4; ++i) upk2(acc[i], ov[2 * i], ov[2 * i + 1]);

    const int n = qbase + q;
    float4* orow = (float4*)(out + (size_t)n * CO + oc);
    orow[0] = make_float4(ov[0], ov[1], ov[2], ov[3]);
    orow[1] = make_float4(ov[4], ov[5], ov[6], ov[7]);

    __syncthreads();                                // done with wc buffers
    float* out_s = wcbuf;                           // alias: [32][64]
    #pragma unroll
    for (int i = 0; i < 8; ++i) out_s[q * 64 + oc + i] = ov[i];
    __syncthreads();

    if (tid < CO) {
        float s = 0.f, s2 = 0.f;
        #pragma unroll
        for (int qq = 0; qq < 32; ++qq) {
            float v = out_s[qq * 64 + tid];
            s += v;
            s2 = fmaf(v, v, s2);
        }
        atomicAdd(&g_sums[tid], s);
        atomicAdd(&g_sumsq[tid], s2);
    }
}

// =============================================================================
// Kernel 2: finalize BN stats into per-channel scale/bias
// =============================================================================
__global__ void finalize_stats_kernel(const float* __restrict__ gamma,
                                      const float* __restrict__ beta) {
    int o = threadIdx.x;
    if (o < CO) {
        const float invN = 1.f / (float)NQ;
        float mean = g_sums[o] * invN;
        float var  = g_sumsq[o] * invN - mean * mean;
        float inv  = rsqrtf(var + 1e-5f);
        float sc   = gamma[o] * inv;
        g_scale[o] = sc;
        g_bias[o]  = fmaf(-mean, sc, beta[o]);
    }
}

// =============================================================================
// Kernel 3: apply BN + LeakyReLU(0.1) in place
// =============================================================================
__global__ void __launch_bounds__(256)
bn_act_kernel(float* __restrict__ out) {
    const int i = blockIdx.x * 256 + threadIdx.x;   // float4 index
    float4 v = ((const float4*)out)[i];
    const int c = (i & 15) * 4;                     // base channel of this float4
    float r0 = fmaf(v.x, g_scale[c + 0], g_bias[c + 0]);
    float r1 = fmaf(v.y, g_scale[c + 1], g_bias[c + 1]);
    float r2 = fmaf(v.z, g_scale[c + 2], g_bias[c + 2]);
    float r3 = fmaf(v.w, g_scale[c + 3], g_bias[c + 3]);
    r0 = (r0 >= 0.f) ? r0 : 0.1f * r0;
    r1 = (r1 >= 0.f) ? r1 : 0.1f * r1;
    r2 = (r2 >= 0.f) ? r2 : 0.1f * r2;
    r3 = (r3 >= 0.f) ? r3 : 0.1f * r3;
    ((float4*)out)[i] = make_float4(r0, r1, r2, r3);
}

// =============================================================================
extern "C" void kernel_launch(void* const* d_in, const int* in_sizes, int n_in,
                              void* d_out, int out_size) {
    const float* x      = (const float*)d_in[0];
    const float* q_pts  = (const float*)d_in[1];
    const float* s_pts  = (const float*)d_in[2];
    const int*   nbr    = (const int*)d_in[3];
    const float* kp     = (const float*)d_in[4];
    const float* Wg     = (const float*)d_in[5];
    const float* gamma  = (const float*)d_in[6];
    const float* beta   = (const float*)d_in[7];
    float*       out    = (float*)d_out;

    cudaFuncSetAttribute(kpconv_main,
                         cudaFuncAttributeMaxDynamicSharedMemorySize, SMEM_TOTAL);

    zero_stats_kernel<<<1, 64>>>();
    kpconv_main<<<NQ / 32, 256, SMEM_TOTAL>>>(x, q_pts, s_pts, nbr, kp, Wg, out);
    finalize_stats_kernel<<<1, 64>>>(gamma, beta);
    bn_act_kernel<<<(NQ * CO / 4) / 256, 256>>>(out);
}

// round 2
// speedup vs baseline: 2.0489x; 2.0489x over previous
#include <cuda_runtime.h>
#include <cstdint>
#include <cstddef>

#define NQ   65536
#define MS   65536
#define HN   32
#define CIN  64
#define CO   64
#define KP   15
#define KTOT 960            // KP * CIN

// ---- 251 MB scratch for weighted[n][k*64+i] (device global: allowed) -------
__device__ float g_wt[(size_t)NQ * KTOT];

// ---- BN scratch -------------------------------------------------------------
__device__ float g_sums[CO];
__device__ float g_sumsq[CO];
__device__ float g_scale[CO];
__device__ float g_bias[CO];

// ---- packed fp32x2 helpers ---------------------------------------------------
static __device__ __forceinline__ unsigned long long pk2(float lo, float hi) {
    unsigned long long r;
    asm("mov.b64 %0, {%1, %2};" : "=l"(r) : "f"(lo), "f"(hi));
    return r;
}
static __device__ __forceinline__ void upk2(unsigned long long v, float &lo, float &hi) {
    asm("mov.b64 {%0, %1}, %2;" : "=f"(lo), "=f"(hi) : "l"(v));
}
static __device__ __forceinline__ unsigned long long ffma2(unsigned long long a,
                                                           unsigned long long b,
                                                           unsigned long long c) {
    unsigned long long d;
    asm("fma.rn.f32x2 %0, %1, %2, %3;" : "=l"(d) : "l"(a), "l"(b), "l"(c));
    return d;
}
static __device__ __forceinline__ float fast_sqrt(float x) {
    float r;
    asm("sqrt.approx.f32 %0, %1;" : "=f"(r) : "f"(x));
    return r;
}

// =============================================================================
// Kernel 0: zero BN accumulators (graph is replayed -> must reset every launch)
// =============================================================================
__global__ void zero_stats_kernel() {
    int t = threadIdx.x;
    if (t < CO) { g_sums[t] = 0.f; g_sumsq[t] = 0.f; }
}

// =============================================================================
// Kernel A: gather + kernel-point influence + aggregation
//   warp per query; writes weighted[n][960] to g_wt
// =============================================================================
__global__ void __launch_bounds__(256)
kpconv_aggregate(const float* __restrict__ x,
                 const float* __restrict__ q_pts,
                 const float* __restrict__ s_pts,
                 const int*   __restrict__ nbr,
                 const float* __restrict__ kp)
{
    __shared__ float4 ws4[8][32][4];   // per-warp influence table: [warp][h][k-quad]
    __shared__ float4 kp4s[16];

    const int tid  = threadIdx.x;
    const int warp = tid >> 5;
    const int lane = tid & 31;

    if (tid < 16) {
        float4 v = make_float4(0.f, 0.f, 0.f, 0.f);
        if (tid < KP) {
            v.x = kp[tid * 3 + 0];
            v.y = kp[tid * 3 + 1];
            v.z = kp[tid * 3 + 2];
        }
        kp4s[tid] = v;
    }
    __syncthreads();

    const double EXT_D = 0.1 * 1.2 / 2.5;
    const float  INV_E = (float)(1.0 / EXT_D);

    const int q = blockIdx.x * 8 + warp;

    const float qx = q_pts[q * 3 + 0];
    const float qy = q_pts[q * 3 + 1];
    const float qz = q_pts[q * 3 + 2];

    const int idx = nbr[q * HN + lane];
    const float rx = s_pts[idx * 3 + 0] - qx;
    const float ry = s_pts[idx * 3 + 1] - qy;
    const float rz = s_pts[idx * 3 + 2] - qz;

    // 15 influences for this lane's neighbor (exact diff^2 form)
    float wv[16];
    #pragma unroll
    for (int k = 0; k < 16; ++k) {
        float w = 0.f;
        if (k < KP) {
            float4 kv = kp4s[k];
            float dx = rx - kv.x, dy = ry - kv.y, dz = rz - kv.z;
            float d2 = fmaf(dx, dx, fmaf(dy, dy, dz * dz));
            float s  = fast_sqrt(d2);
            w = fmaxf(fmaf(s, -INV_E, 1.f), 0.f);
        }
        wv[k] = w;
    }
    ws4[warp][lane][0] = make_float4(wv[0],  wv[1],  wv[2],  wv[3]);
    ws4[warp][lane][1] = make_float4(wv[4],  wv[5],  wv[6],  wv[7]);
    ws4[warp][lane][2] = make_float4(wv[8],  wv[9],  wv[10], wv[11]);
    ws4[warp][lane][3] = make_float4(wv[12], wv[13], wv[14], wv[15]);
    __syncwarp();

    // accumulate weighted[k, i]; lane owns i = {2*lane, 2*lane+1}
    // acc0[p] = {weighted[2p][i0], weighted[2p+1][i0]}
    unsigned long long acc0[8], acc1[8];
    #pragma unroll
    for (int p = 0; p < 8; ++p) { acc0[p] = 0ULL; acc1[p] = 0ULL; }

    #pragma unroll 4
    for (int h = 0; h < HN; ++h) {
        const int ih = __shfl_sync(0xffffffffu, idx, h);
        const float2 xv = *(const float2*)(x + (size_t)ih * CIN + 2 * lane);
        const unsigned long long x0 = pk2(xv.x, xv.x);
        const unsigned long long x1 = pk2(xv.y, xv.y);
        const ulonglong2* wsv = (const ulonglong2*)&ws4[warp][h][0];
        #pragma unroll
        for (int pp = 0; pp < 4; ++pp) {
            ulonglong2 wp = wsv[pp];
            acc0[2 * pp]     = ffma2(wp.x, x0, acc0[2 * pp]);
            acc1[2 * pp]     = ffma2(wp.x, x1, acc1[2 * pp]);
            acc0[2 * pp + 1] = ffma2(wp.y, x0, acc0[2 * pp + 1]);
            acc1[2 * pp + 1] = ffma2(wp.y, x1, acc1[2 * pp + 1]);
        }
    }

    // write weighted row (coalesced 256B per k)
    float* wq = g_wt + (size_t)q * KTOT;
    #pragma unroll
    for (int p = 0; p < 8; ++p) {
        float a0lo, a0hi, a1lo, a1hi;
        upk2(acc0[p], a0lo, a0hi);
        upk2(acc1[p], a1lo, a1hi);
        const int k0 = 2 * p, k1 = 2 * p + 1;
        *(float2*)(wq + k0 * 64 + 2 * lane) = make_float2(a0lo, a1lo);
        if (k1 < KP)
            *(float2*)(wq + k1 * 64 + 2 * lane) = make_float2(a0hi, a1hi);
    }
}

// =============================================================================
// Kernel B: out[65536,64] = g_wt[65536,960] x W[960,64]  + BN partial sums
//   M-tile 128, K chunks of 64 (double buffered), A transposed in SMEM
// =============================================================================
#define SMA_STRIDE 132
#define SMA_BUF    (64 * SMA_STRIDE)                 // floats per A buffer
#define SMW_BUF    (64 * 64)                         // floats per W buffer
#define SMB_TOTAL  ((2 * SMA_BUF + 2 * SMW_BUF) * 4) // bytes

extern __shared__ float smB[];

__global__ void __launch_bounds__(256, 2)
kpconv_gemm(const float* __restrict__ Wg,
            float*       __restrict__ out)
{
    float* sa0 = smB;
    float* sa1 = smB + SMA_BUF;
    float* sw0 = smB + 2 * SMA_BUF;
    float* sw1 = sw0 + SMW_BUF;

    const int tid   = threadIdx.x;
    const int qbase = blockIdx.x * 128;

    const int qg = tid >> 3;          // 0..31 : group of 4 queries
    const int og = tid & 7;           // 0..7  : group of 8 out channels
    const int oc = og * 8;

    // loader mapping for A chunk: row q, 32-col half
    const int lq = tid >> 1;
    const int lh = (tid & 1) * 32;
    const float* a_src_base = g_wt + (size_t)(qbase + lq) * KTOT + lh;
    const float4* Wg4 = (const float4*)Wg;           // 15 chunks x 1024 float4

    // ---- preload chunk 0 ----
    {
        float4 pa[8];
        #pragma unroll
        for (int f = 0; f < 8; ++f) pa[f] = *(const float4*)(a_src_base + f * 4);
        #pragma unroll
        for (int f = 0; f < 8; ++f) {
            sa0[(lh + f * 4 + 0) * SMA_STRIDE + lq] = pa[f].x;
            sa0[(lh + f * 4 + 1) * SMA_STRIDE + lq] = pa[f].y;
            sa0[(lh + f * 4 + 2) * SMA_STRIDE + lq] = pa[f].z;
            sa0[(lh + f * 4 + 3) * SMA_STRIDE + lq] = pa[f].w;
        }
        float4 pw[4];
        #pragma unroll
        for (int i = 0; i < 4; ++i) pw[i] = Wg4[tid + 256 * i];
        #pragma unroll
        for (int i = 0; i < 4; ++i) ((float4*)sw0)[tid + 256 * i] = pw[i];
    }
    __syncthreads();

    unsigned long long acc[4][4];
    #pragma unroll
    for (int r = 0; r < 4; ++r)
        #pragma unroll
        for (int m = 0; m < 4; ++m) acc[r][m] = 0ULL;

    #pragma unroll 1
    for (int c = 0; c < 15; ++c) {
        const float* sa = (c & 1) ? sa1 : sa0;
        const float* sw = (c & 1) ? sw1 : sw0;

        // prefetch next chunk into registers (overlaps with compute below)
        float4 pa[8], pw[4];
        if (c < 14) {
            const float* as = a_src_base + (c + 1) * 64;
            #pragma unroll
            for (int f = 0; f < 8; ++f) pa[f] = *(const float4*)(as + f * 4);
            #pragma unroll
            for (int i = 0; i < 4; ++i) pw[i] = Wg4[(c + 1) * 1024 + tid + 256 * i];
        }

        #pragma unroll 8
        for (int j = 0; j < 64; ++j) {
            const float4 av = *(const float4*)(sa + j * SMA_STRIDE + qg * 4);
            const ulonglong2* wrow = (const ulonglong2*)(sw + j * 64 + oc);
            const ulonglong2 w01 = wrow[0];
            const ulonglong2 w23 = wrow[1];
            const unsigned long long a0 = pk2(av.x, av.x);
            const unsigned long long a1 = pk2(av.y, av.y);
            const unsigned long long a2 = pk2(av.z, av.z);
            const unsigned long long a3 = pk2(av.w, av.w);
            acc[0][0] = ffma2(a0, w01.x, acc[0][0]);
            acc[0][1] = ffma2(a0, w01.y, acc[0][1]);
            acc[0][2] = ffma2(a0, w23.x, acc[0][2]);
            acc[0][3] = ffma2(a0, w23.y, acc[0][3]);
            acc[1][0] = ffma2(a1, w01.x, acc[1][0]);
            acc[1][1] = ffma2(a1, w01.y, acc[1][1]);
            acc[1][2] = ffma2(a1, w23.x, acc[1][2]);
            acc[1][3] = ffma2(a1, w23.y, acc[1][3]);
            acc[2][0] = ffma2(a2, w01.x, acc[2][0]);
            acc[2][1] = ffma2(a2, w01.y, acc[2][1]);
            acc[2][2] = ffma2(a2, w23.x, acc[2][2]);
            acc[2][3] = ffma2(a2, w23.y, acc[2][3]);
            acc[3][0] = ffma2(a3, w01.x, acc[3][0]);
            acc[3][1] = ffma2(a3, w01.y, acc[3][1]);
            acc[3][2] = ffma2(a3, w23.x, acc[3][2]);
            acc[3][3] = ffma2(a3, w23.y, acc[3][3]);
        }

        if (c < 14) {
            float* san = (c & 1) ? sa0 : sa1;
            float* swn = (c & 1) ? sw0 : sw1;
            #pragma unroll
            for (int f = 0; f < 8; ++f) {
                san[(lh + f * 4 + 0) * SMA_STRIDE + lq] = pa[f].x;
                san[(lh + f * 4 + 1) * SMA_STRIDE + lq] = pa[f].y;
                san[(lh + f * 4 + 2) * SMA_STRIDE + lq] = pa[f].z;
                san[(lh + f * 4 + 3) * SMA_STRIDE + lq] = pa[f].w;
            }
            #pragma unroll
            for (int i = 0; i < 4; ++i) ((float4*)swn)[tid + 256 * i] = pw[i];
            __syncthreads();
        }
    }

    // ---- write outputs + BN partial sums ----
    float ov[4][8];
    float ps[8], ps2[8];
    #pragma unroll
    for (int e = 0; e < 8; ++e) { ps[e] = 0.f; ps2[e] = 0.f; }

    #pragma unroll
    for (int r = 0; r < 4; ++r) {
        #pragma unroll
        for (int m = 0; m < 4; ++m) upk2(acc[r][m], ov[r][2 * m], ov[r][2 * m + 1]);
        const int n = qbase + qg * 4 + r;
        float4* orow = (float4*)(out + (size_t)n * CO + oc);
        orow[0] = make_float4(ov[r][0], ov[r][1], ov[r][2], ov[r][3]);
        orow[1] = make_float4(ov[r][4], ov[r][5], ov[r][6], ov[r][7]);
        #pragma unroll
        for (int e = 0; e < 8; ++e) {
            ps[e] += ov[r][e];
            ps2[e] = fmaf(ov[r][e], ov[r][e], ps2[e]);
        }
    }

    __syncthreads();                           // done with A/W buffers
    float* red  = smB;                         // [32][64]
    float* red2 = smB + 32 * 64;               // [32][64]
    #pragma unroll
    for (int e = 0; e < 8; ++e) {
        red [qg * 64 + oc + e] = ps[e];
        red2[qg * 64 + oc + e] = ps2[e];
    }
    __syncthreads();

    if (tid < CO) {
        float s = 0.f, s2 = 0.f;
        #pragma unroll
        for (int g = 0; g < 32; ++g) {
            s  += red [g * 64 + tid];
            s2 += red2[g * 64 + tid];
        }
        atomicAdd(&g_sums[tid], s);
        atomicAdd(&g_sumsq[tid], s2);
    }
}

// =============================================================================
// Kernel 2: finalize BN stats
// =============================================================================
__global__ void finalize_stats_kernel(const float* __restrict__ gamma,
                                      const float* __restrict__ beta) {
    int o = threadIdx.x;
    if (o < CO) {
        const float invN = 1.f / (float)NQ;
        float mean = g_sums[o] * invN;
        float var  = g_sumsq[o] * invN - mean * mean;
        float inv  = rsqrtf(var + 1e-5f);
        float sc   = gamma[o] * inv;
        g_scale[o] = sc;
        g_bias[o]  = fmaf(-mean, sc, beta[o]);
    }
}

// =============================================================================
// Kernel 3: apply BN + LeakyReLU(0.1) in place
// =============================================================================
__global__ void __launch_bounds__(256)
bn_act_kernel(float* __restrict__ out) {
    const int i = blockIdx.x * 256 + threadIdx.x;   // float4 index
    float4 v = ((const float4*)out)[i];
    const int c = (i & 15) * 4;
    float r0 = fmaf(v.x, g_scale[c + 0], g_bias[c + 0]);
    float r1 = fmaf(v.y, g_scale[c + 1], g_bias[c + 1]);
    float r2 = fmaf(v.z, g_scale[c + 2], g_bias[c + 2]);
    float r3 = fmaf(v.w, g_scale[c + 3], g_bias[c + 3]);
    r0 = (r0 >= 0.f) ? r0 : 0.1f * r0;
    r1 = (r1 >= 0.f) ? r1 : 0.1f * r1;
    r2 = (r2 >= 0.f) ? r2 : 0.1f * r2;
    r3 = (r3 >= 0.f) ? r3 : 0.1f * r3;
    ((float4*)out)[i] = make_float4(r0, r1, r2, r3);
}

// =============================================================================
extern "C" void kernel_launch(void* const* d_in, const int* in_sizes, int n_in,
                              void* d_out, int out_size) {
    const float* x      = (const float*)d_in[0];
    const float* q_pts  = (const float*)d_in[1];
    const float* s_pts  = (const float*)d_in[2];
    const int*   nbr    = (const int*)d_in[3];
    const float* kp     = (const float*)d_in[4];
    const float* Wg     = (const float*)d_in[5];
    const float* gamma  = (const float*)d_in[6];
    const float* beta   = (const float*)d_in[7];
    float*       out    = (float*)d_out;

    cudaFuncSetAttribute(kpconv_gemm,
                         cudaFuncAttributeMaxDynamicSharedMemorySize, SMB_TOTAL);

    zero_stats_kernel<<<1, 64>>>();
    kpconv_aggregate<<<NQ / 8, 256>>>(x, q_pts, s_pts, nbr, kp);
    kpconv_gemm<<<NQ / 128, 256, SMB_TOTAL>>>(Wg, out);
    finalize_stats_kernel<<<1, 64>>>(gamma, beta);
    bn_act_kernel<<<(NQ * CO / 4) / 256, 256>>>(out);
}

// round 3
// speedup vs baseline: 2.4964x; 1.2184x over previous
#include <cuda_runtime.h>
#include <cstdint>
#include <cstddef>

#define NQ   65536
#define MS   65536
#define HN   32
#define CIN  64
#define CO   64
#define KP   15
#define KTOT 960            // KP * CIN

// ---- 251 MB scratch for weighted[n][k*64+i] ---------------------------------
__device__ float g_wt[(size_t)NQ * KTOT];

// ---- BN scratch -------------------------------------------------------------
__device__ float g_sums[CO];
__device__ float g_sumsq[CO];
__device__ float g_scale[CO];
__device__ float g_bias[CO];

// ---- packed fp32x2 helpers ---------------------------------------------------
static __device__ __forceinline__ unsigned long long pk2(float lo, float hi) {
    unsigned long long r;
    asm("mov.b64 %0, {%1, %2};" : "=l"(r) : "f"(lo), "f"(hi));
    return r;
}
static __device__ __forceinline__ void upk2(unsigned long long v, float &lo, float &hi) {
    asm("mov.b64 {%0, %1}, %2;" : "=f"(lo), "=f"(hi) : "l"(v));
}
static __device__ __forceinline__ unsigned long long ffma2(unsigned long long a,
                                                           unsigned long long b,
                                                           unsigned long long c) {
    unsigned long long d;
    asm("fma.rn.f32x2 %0, %1, %2, %3;" : "=l"(d) : "l"(a), "l"(b), "l"(c));
    return d;
}
static __device__ __forceinline__ float fast_sqrt(float x) {
    float r;
    asm("sqrt.approx.f32 %0, %1;" : "=f"(r) : "f"(x));
    return r;
}
static __device__ __forceinline__ void cp_async16(uint32_t smem_dst, const void* gmem_src) {
    asm volatile("cp.async.cg.shared.global [%0], [%1], 16;"
                 :: "r"(smem_dst), "l"(gmem_src));
}
static __device__ __forceinline__ void cp_commit() {
    asm volatile("cp.async.commit_group;");
}
static __device__ __forceinline__ void cp_wait0() {
    asm volatile("cp.async.wait_group 0;");
}

// =============================================================================
// Kernel A: gather + kernel-point influence + aggregation (warp per query)
//   also zeroes BN accumulators (block 0) — B's atomics run strictly after.
// =============================================================================
__global__ void __launch_bounds__(256)
kpconv_aggregate(const float* __restrict__ x,
                 const float* __restrict__ q_pts,
                 const float* __restrict__ s_pts,
                 const int*   __restrict__ nbr,
                 const float* __restrict__ kp)
{
    __shared__ float4 ws4[8][32][4];   // [warp][h][k-quad]
    __shared__ float4 kp4s[16];

    const int tid  = threadIdx.x;
    const int warp = tid >> 5;
    const int lane = tid & 31;

    if (blockIdx.x == 0 && tid < CO) { g_sums[tid] = 0.f; g_sumsq[tid] = 0.f; }

    if (tid < 16) {
        float4 v = make_float4(0.f, 0.f, 0.f, 0.f);
        if (tid < KP) {
            v.x = kp[tid * 3 + 0];
            v.y = kp[tid * 3 + 1];
            v.z = kp[tid * 3 + 2];
        }
        kp4s[tid] = v;
    }
    __syncthreads();

    const double EXT_D = 0.1 * 1.2 / 2.5;
    const float  INV_E = (float)(1.0 / EXT_D);

    const int q = blockIdx.x * 8 + warp;

    const float qx = q_pts[q * 3 + 0];
    const float qy = q_pts[q * 3 + 1];
    const float qz = q_pts[q * 3 + 2];

    const int idx = nbr[q * HN + lane];
    const float rx = s_pts[idx * 3 + 0] - qx;
    const float ry = s_pts[idx * 3 + 1] - qy;
    const float rz = s_pts[idx * 3 + 2] - qz;

    float wv[16];
    #pragma unroll
    for (int k = 0; k < 16; ++k) {
        float w = 0.f;
        if (k < KP) {
            float4 kv = kp4s[k];
            float dx = rx - kv.x, dy = ry - kv.y, dz = rz - kv.z;
            float d2 = fmaf(dx, dx, fmaf(dy, dy, dz * dz));
            float s  = fast_sqrt(d2);
            w = fmaxf(fmaf(s, -INV_E, 1.f), 0.f);
        }
        wv[k] = w;
    }
    ws4[warp][lane][0] = make_float4(wv[0],  wv[1],  wv[2],  wv[3]);
    ws4[warp][lane][1] = make_float4(wv[4],  wv[5],  wv[6],  wv[7]);
    ws4[warp][lane][2] = make_float4(wv[8],  wv[9],  wv[10], wv[11]);
    ws4[warp][lane][3] = make_float4(wv[12], wv[13], wv[14], wv[15]);
    __syncwarp();

    unsigned long long acc0[8], acc1[8];
    #pragma unroll
    for (int p = 0; p < 8; ++p) { acc0[p] = 0ULL; acc1[p] = 0ULL; }

    #pragma unroll 8
    for (int h = 0; h < HN; ++h) {
        const int ih = __shfl_sync(0xffffffffu, idx, h);
        const float2 xv = *(const float2*)(x + (size_t)ih * CIN + 2 * lane);
        const unsigned long long x0 = pk2(xv.x, xv.x);
        const unsigned long long x1 = pk2(xv.y, xv.y);
        const ulonglong2* wsv = (const ulonglong2*)&ws4[warp][h][0];
        #pragma unroll
        for (int pp = 0; pp < 4; ++pp) {
            ulonglong2 wp = wsv[pp];
            acc0[2 * pp]     = ffma2(wp.x, x0, acc0[2 * pp]);
            acc1[2 * pp]     = ffma2(wp.x, x1, acc1[2 * pp]);
            acc0[2 * pp + 1] = ffma2(wp.y, x0, acc0[2 * pp + 1]);
            acc1[2 * pp + 1] = ffma2(wp.y, x1, acc1[2 * pp + 1]);
        }
    }

    float* wq = g_wt + (size_t)q * KTOT;
    #pragma unroll
    for (int p = 0; p < 8; ++p) {
        float a0lo, a0hi, a1lo, a1hi;
        upk2(acc0[p], a0lo, a0hi);
        upk2(acc1[p], a1lo, a1hi);
        const int k0 = 2 * p, k1 = 2 * p + 1;
        *(float2*)(wq + k0 * 64 + 2 * lane) = make_float2(a0lo, a1lo);
        if (k1 < KP)
            *(float2*)(wq + k1 * 64 + 2 * lane) = make_float2(a0hi, a1hi);
    }
}

// =============================================================================
// Kernel B: out[65536,64] = g_wt[65536,960] x W[960,64] + BN partial sums
//   CTA = 128 threads, M-tile 128, thread tile 8q x 8oc
//   A: LDG reg prefetch -> transposed STS (stride 132), double buffered
//   W: cp.async double buffered
// =============================================================================
#define SMA_STRIDE 132
#define SMA_BUF    (64 * SMA_STRIDE)                 // 8448 floats
#define SMW_BUF    (64 * 64)                         // 4096 floats
#define SMB_TOTAL  ((2 * SMA_BUF + 2 * SMW_BUF) * 4) // 100352 bytes

extern __shared__ float smB[];

__global__ void __launch_bounds__(128, 2)
kpconv_gemm(const float* __restrict__ Wg,
            float*       __restrict__ out)
{
    float* sa[2] = { smB, smB + SMA_BUF };
    float* sw[2] = { smB + 2 * SMA_BUF, smB + 2 * SMA_BUF + SMW_BUF };

    const int tid   = threadIdx.x;
    const int qbase = blockIdx.x * 128;
    const int qg    = tid >> 3;        // 0..15 : group of 8 queries
    const int oc    = (tid & 7) * 8;   // 8 out channels

    const float4* a_src = (const float4*)(g_wt + (size_t)(qbase + tid) * KTOT);
    const float4* Wg4   = (const float4*)Wg;     // 15 chunks x 1024 float4

    const uint32_t sw_smem[2] = {
        (uint32_t)__cvta_generic_to_shared(sw[0]),
        (uint32_t)__cvta_generic_to_shared(sw[1])
    };

    // ---- prologue: stage chunk 0 ----
    {
        #pragma unroll
        for (int i = 0; i < 8; ++i)
            cp_async16(sw_smem[0] + (tid + 128 * i) * 16, Wg4 + tid + 128 * i);
        cp_commit();

        float4 pa[16];
        #pragma unroll
        for (int f = 0; f < 16; ++f) pa[f] = a_src[f];
        #pragma unroll
        for (int f = 0; f < 16; ++f) {
            sa[0][(f * 4 + 0) * SMA_STRIDE + tid] = pa[f].x;
            sa[0][(f * 4 + 1) * SMA_STRIDE + tid] = pa[f].y;
            sa[0][(f * 4 + 2) * SMA_STRIDE + tid] = pa[f].z;
            sa[0][(f * 4 + 3) * SMA_STRIDE + tid] = pa[f].w;
        }
        cp_wait0();
    }
    __syncthreads();

    unsigned long long acc[8][4];
    #pragma unroll
    for (int r = 0; r < 8; ++r)
        #pragma unroll
        for (int m = 0; m < 4; ++m) acc[r][m] = 0ULL;

    #pragma unroll 1
    for (int c = 0; c < 15; ++c) {
        const int cur = c & 1, nxt = cur ^ 1;
        const float* sac = sa[cur];
        const float* swc = sw[cur];

        float4 pa[16];
        if (c < 14) {
            #pragma unroll
            for (int i = 0; i < 8; ++i)
                cp_async16(sw_smem[nxt] + (tid + 128 * i) * 16,
                           Wg4 + (c + 1) * 1024 + tid + 128 * i);
            cp_commit();
            #pragma unroll
            for (int f = 0; f < 16; ++f) pa[f] = a_src[(c + 1) * 16 + f];
        }

        #pragma unroll 4
        for (int j = 0; j < 64; ++j) {
            const float4 af0 = *(const float4*)(sac + j * SMA_STRIDE + qg * 8);
            const float4 af1 = *(const float4*)(sac + j * SMA_STRIDE + qg * 8 + 4);
            const ulonglong2 w01 = *(const ulonglong2*)(swc + j * 64 + oc);
            const ulonglong2 w23 = *(const ulonglong2*)(swc + j * 64 + oc + 4);
            const unsigned long long a0 = pk2(af0.x, af0.x);
            const unsigned long long a1 = pk2(af0.y, af0.y);
            const unsigned long long a2 = pk2(af0.z, af0.z);
            const unsigned long long a3 = pk2(af0.w, af0.w);
            const unsigned long long a4 = pk2(af1.x, af1.x);
            const unsigned long long a5 = pk2(af1.y, af1.y);
            const unsigned long long a6 = pk2(af1.z, af1.z);
            const unsigned long long a7 = pk2(af1.w, af1.w);
            acc[0][0] = ffma2(a0, w01.x, acc[0][0]);
            acc[0][1] = ffma2(a0, w01.y, acc[0][1]);
            acc[0][2] = ffma2(a0, w23.x, acc[0][2]);
            acc[0][3] = ffma2(a0, w23.y, acc[0][3]);
            acc[1][0] = ffma2(a1, w01.x, acc[1][0]);
            acc[1][1] = ffma2(a1, w01.y, acc[1][1]);
            acc[1][2] = ffma2(a1, w23.x, acc[1][2]);
            acc[1][3] = ffma2(a1, w23.y, acc[1][3]);
            acc[2][0] = ffma2(a2, w01.x, acc[2][0]);
            acc[2][1] = ffma2(a2, w01.y, acc[2][1]);
            acc[2][2] = ffma2(a2, w23.x, acc[2][2]);
            acc[2][3] = ffma2(a2, w23.y, acc[2][3]);
            acc[3][0] = ffma2(a3, w01.x, acc[3][0]);
            acc[3][1] = ffma2(a3, w01.y, acc[3][1]);
            acc[3][2] = ffma2(a3, w23.x, acc[3][2]);
            acc[3][3] = ffma2(a3, w23.y, acc[3][3]);
            acc[4][0] = ffma2(a4, w01.x, acc[4][0]);
            acc[4][1] = ffma2(a4, w01.y, acc[4][1]);
            acc[4][2] = ffma2(a4, w23.x, acc[4][2]);
            acc[4][3] = ffma2(a4, w23.y, acc[4][3]);
            acc[5][0] = ffma2(a5, w01.x, acc[5][0]);
            acc[5][1] = ffma2(a5, w01.y, acc[5][1]);
            acc[5][2] = ffma2(a5, w23.x, acc[5][2]);
            acc[5][3] = ffma2(a5, w23.y, acc[5][3]);
            acc[6][0] = ffma2(a6, w01.x, acc[6][0]);
            acc[6][1] = ffma2(a6, w01.y, acc[6][1]);
            acc[6][2] = ffma2(a6, w23.x, acc[6][2]);
            acc[6][3] = ffma2(a6, w23.y, acc[6][3]);
            acc[7][0] = ffma2(a7, w01.x, acc[7][0]);
            acc[7][1] = ffma2(a7, w01.y, acc[7][1]);
            acc[7][2] = ffma2(a7, w23.x, acc[7][2]);
            acc[7][3] = ffma2(a7, w23.y, acc[7][3]);
        }

        if (c < 14) {
            float* san = sa[nxt];
            #pragma unroll
            for (int f = 0; f < 16; ++f) {
                san[(f * 4 + 0) * SMA_STRIDE + tid] = pa[f].x;
                san[(f * 4 + 1) * SMA_STRIDE + tid] = pa[f].y;
                san[(f * 4 + 2) * SMA_STRIDE + tid] = pa[f].z;
                san[(f * 4 + 3) * SMA_STRIDE + tid] = pa[f].w;
            }
            cp_wait0();
            __syncthreads();
        }
    }

    // ---- epilogue: write raw out + BN partial sums ----
    float ps[8], ps2[8];
    #pragma unroll
    for (int e = 0; e < 8; ++e) { ps[e] = 0.f; ps2[e] = 0.f; }

    #pragma unroll
    for (int r = 0; r < 8; ++r) {
        float ov[8];
        #pragma unroll
        for (int m = 0; m < 4; ++m) upk2(acc[r][m], ov[2 * m], ov[2 * m + 1]);
        const int n = qbase + qg * 8 + r;
        float4* orow = (float4*)(out + (size_t)n * CO + oc);
        orow[0] = make_float4(ov[0], ov[1], ov[2], ov[3]);
        orow[1] = make_float4(ov[4], ov[5], ov[6], ov[7]);
        #pragma unroll
        for (int e = 0; e < 8; ++e) {
            ps[e] += ov[e];
            ps2[e] = fmaf(ov[e], ov[e], ps2[e]);
        }
    }

    __syncthreads();                          // done with A/W buffers
    float* red  = smB;                        // [16][64]
    float* red2 = smB + 16 * 64;              // [16][64]
    #pragma unroll
    for (int e = 0; e < 8; ++e) {
        red [qg * 64 + oc + e] = ps[e];
        red2[qg * 64 + oc + e] = ps2[e];
    }
    __syncthreads();

    if (tid < CO) {
        float s = 0.f, s2 = 0.f;
        #pragma unroll
        for (int g = 0; g < 16; ++g) {
            s  += red [g * 64 + tid];
            s2 += red2[g * 64 + tid];
        }
        atomicAdd(&g_sums[tid], s);
        atomicAdd(&g_sumsq[tid], s2);
    }
}

// =============================================================================
// Kernel: finalize BN stats
// =============================================================================
__global__ void finalize_stats_kernel(const float* __restrict__ gamma,
                                      const float* __restrict__ beta) {
    int o = threadIdx.x;
    if (o < CO) {
        const float invN = 1.f / (float)NQ;
        float mean = g_sums[o] * invN;
        float var  = g_sumsq[o] * invN - mean * mean;
        float inv  = rsqrtf(var + 1e-5f);
        float sc   = gamma[o] * inv;
        g_scale[o] = sc;
        g_bias[o]  = fmaf(-mean, sc, beta[o]);
    }
}

// =============================================================================
// Kernel: apply BN + LeakyReLU(0.1) in place
// =============================================================================
__global__ void __launch_bounds__(256)
bn_act_kernel(float* __restrict__ out) {
    const int i = blockIdx.x * 256 + threadIdx.x;   // float4 index
    float4 v = ((const float4*)out)[i];
    const int c = (i & 15) * 4;
    float r0 = fmaf(v.x, g_scale[c + 0], g_bias[c + 0]);
    float r1 = fmaf(v.y, g_scale[c + 1], g_bias[c + 1]);
    float r2 = fmaf(v.z, g_scale[c + 2], g_bias[c + 2]);
    float r3 = fmaf(v.w, g_scale[c + 3], g_bias[c + 3]);
    r0 = (r0 >= 0.f) ? r0 : 0.1f * r0;
    r1 = (r1 >= 0.f) ? r1 : 0.1f * r1;
    r2 = (r2 >= 0.f) ? r2 : 0.1f * r2;
    r3 = (r3 >= 0.f) ? r3 : 0.1f * r3;
    ((float4*)out)[i] = make_float4(r0, r1, r2, r3);
}

// =============================================================================
extern "C" void kernel_launch(void* const* d_in, const int* in_sizes, int n_in,
                              void* d_out, int out_size) {
    const float* x      = (const float*)d_in[0];
    const float* q_pts  = (const float*)d_in[1];
    const float* s_pts  = (const float*)d_in[2];
    const int*   nbr    = (const int*)d_in[3];
    const float* kp     = (const float*)d_in[4];
    const float* Wg     = (const float*)d_in[5];
    const float* gamma  = (const float*)d_in[6];
    const float* beta   = (const float*)d_in[7];
    float*       out    = (float*)d_out;

    cudaFuncSetAttribute(kpconv_gemm,
                         cudaFuncAttributeMaxDynamicSharedMemorySize, SMB_TOTAL);

    kpconv_aggregate<<<NQ / 8, 256>>>(x, q_pts, s_pts, nbr, kp);
    kpconv_gemm<<<NQ / 128, 128, SMB_TOTAL>>>(Wg, out);
    finalize_stats_kernel<<<1, 64>>>(gamma, beta);
    bn_act_kernel<<<(NQ * CO / 4) / 256, 256>>>(out);
}

// round 5
// speedup vs baseline: 4.9287x; 1.9743x over previous
#include <cuda_runtime.h>
#include <cuda_bf16.h>
#include <cstdint>
#include <cstddef>

#define NQ   65536
#define MS   65536
#define HN   32
#define CIN  64
#define CO   64
#define KP   15
#define KTOT 960            // KP * CIN

// ---- device scratch ----------------------------------------------------------
__device__ __nv_bfloat16 g_wth[(size_t)NQ * KTOT];   // weighted, bf16 hi
__device__ __nv_bfloat16 g_wtl[(size_t)NQ * KTOT];   // weighted, bf16 lo
__device__ __nv_bfloat16 g_Wth[(size_t)CO * KTOT];   // W^T [o][k*64+i], bf16 hi
__device__ __nv_bfloat16 g_Wtl[(size_t)CO * KTOT];   // W^T, bf16 lo

__device__ float g_sums[CO];
__device__ float g_sumsq[CO];
__device__ float g_scale[CO];
__device__ float g_bias[CO];

// ---- fp32x2 helpers (aggregation kernel) --------------------------------------
static __device__ __forceinline__ unsigned long long pk2(float lo, float hi) {
    unsigned long long r;
    asm("mov.b64 %0, {%1, %2};" : "=l"(r) : "f"(lo), "f"(hi));
    return r;
}
static __device__ __forceinline__ void upk2(unsigned long long v, float &lo, float &hi) {
    asm("mov.b64 {%0, %1}, %2;" : "=f"(lo), "=f"(hi) : "l"(v));
}
static __device__ __forceinline__ unsigned long long ffma2(unsigned long long a,
                                                           unsigned long long b,
                                                           unsigned long long c) {
    unsigned long long d;
    asm("fma.rn.f32x2 %0, %1, %2, %3;" : "=l"(d) : "l"(a), "l"(b), "l"(c));
    return d;
}
static __device__ __forceinline__ float fast_sqrt(float x) {
    float r;
    asm("sqrt.approx.f32 %0, %1;" : "=f"(r) : "f"(x));
    return r;
}

// ---- cp.async -----------------------------------------------------------------
static __device__ __forceinline__ void cp_async16(uint32_t smem_dst, const void* gmem_src) {
    asm volatile("cp.async.cg.shared.global [%0], [%1], 16;"
                 :: "r"(smem_dst), "l"(gmem_src));
}
static __device__ __forceinline__ void cp_commit() { asm volatile("cp.async.commit_group;"); }
static __device__ __forceinline__ void cp_wait0()  { asm volatile("cp.async.wait_group 0;"); }
static __device__ __forceinline__ void cp_wait1()  { asm volatile("cp.async.wait_group 1;"); }

static __device__ __forceinline__ uint32_t smem_u32(const void* p) {
    uint32_t a;
    asm("{ .reg .u64 t; cvta.to.shared.u64 t, %1; cvt.u32.u64 %0, t; }" : "=r"(a) : "l"(p));
    return a;
}

// ---- HMMA building blocks (plain sm_80+ PTX: legal on sm_103 non-a) ------------
#define SWZ128(b)   ((b) ^ (((b) >> 3) & 0x70))

#define LDSM4(r0, r1, r2, r3, addr) \
    asm volatile("ldmatrix.sync.aligned.m8n8.x4.shared.b16 {%0,%1,%2,%3}, [%4];" \
        : "=r"(r0), "=r"(r1), "=r"(r2), "=r"(r3) : "r"(addr))

#define MMA16816(c, a0, a1, a2, a3, b0, b1) \
    asm volatile("mma.sync.aligned.m16n8k16.row.col.f32.bf16.bf16.f32 " \
        "{%0,%1,%2,%3}, {%4,%5,%6,%7}, {%8,%9}, {%0,%1,%2,%3};" \
        : "+f"((c)[0]), "+f"((c)[1]), "+f"((c)[2]), "+f"((c)[3]) \
        : "r"(a0), "r"(a1), "r"(a2), "r"(a3), "r"(b0), "r"(b1))

// =============================================================================
// Kernel P: split/transpose W -> Wt[o][k*64+i] bf16 hi/lo
// =============================================================================
__global__ void __launch_bounds__(64)
prep_w(const float* __restrict__ Wg) {
    const int ki = blockIdx.x;              // 0..959
    const int o  = threadIdx.x;             // 0..63
    float w = Wg[ki * 64 + o];
    __nv_bfloat16 hi = __float2bfloat16(w);
    __nv_bfloat16 lo = __float2bfloat16(w - __bfloat162float(hi));
    g_Wth[(size_t)o * KTOT + ki] = hi;
    g_Wtl[(size_t)o * KTOT + ki] = lo;
}

// =============================================================================
// Kernel A: gather + influence + aggregation (warp per query) -> bf16 hi/lo
// =============================================================================
__global__ void __launch_bounds__(256)
kpconv_aggregate(const float* __restrict__ x,
                 const float* __restrict__ q_pts,
                 const float* __restrict__ s_pts,
                 const int*   __restrict__ nbr,
                 const float* __restrict__ kp)
{
    __shared__ float4 ws4[8][32][4];
    __shared__ float4 kp4s[16];

    const int tid  = threadIdx.x;
    const int warp = tid >> 5;
    const int lane = tid & 31;

    if (blockIdx.x == 0 && tid < CO) { g_sums[tid] = 0.f; g_sumsq[tid] = 0.f; }

    if (tid < 16) {
        float4 v = make_float4(0.f, 0.f, 0.f, 0.f);
        if (tid < KP) {
            v.x = kp[tid * 3 + 0];
            v.y = kp[tid * 3 + 1];
            v.z = kp[tid * 3 + 2];
        }
        kp4s[tid] = v;
    }
    __syncthreads();

    const double EXT_D = 0.1 * 1.2 / 2.5;
    const float  INV_E = (float)(1.0 / EXT_D);

    const int q = blockIdx.x * 8 + warp;

    const float qx = q_pts[q * 3 + 0];
    const float qy = q_pts[q * 3 + 1];
    const float qz = q_pts[q * 3 + 2];

    const int idx = nbr[q * HN + lane];
    const float rx = s_pts[idx * 3 + 0] - qx;
    const float ry = s_pts[idx * 3 + 1] - qy;
    const float rz = s_pts[idx * 3 + 2] - qz;

    float wv[16];
    #pragma unroll
    for (int k = 0; k < 16; ++k) {
        float w = 0.f;
        if (k < KP) {
            float4 kv = kp4s[k];
            float dx = rx - kv.x, dy = ry - kv.y, dz = rz - kv.z;
            float d2 = fmaf(dx, dx, fmaf(dy, dy, dz * dz));
            float s  = fast_sqrt(d2);
            w = fmaxf(fmaf(s, -INV_E, 1.f), 0.f);
        }
        wv[k] = w;
    }
    ws4[warp][lane][0] = make_float4(wv[0],  wv[1],  wv[2],  wv[3]);
    ws4[warp][lane][1] = make_float4(wv[4],  wv[5],  wv[6],  wv[7]);
    ws4[warp][lane][2] = make_float4(wv[8],  wv[9],  wv[10], wv[11]);
    ws4[warp][lane][3] = make_float4(wv[12], wv[13], wv[14], wv[15]);
    __syncwarp();

    unsigned long long acc0[8], acc1[8];
    #pragma unroll
    for (int p = 0; p < 8; ++p) { acc0[p] = 0ULL; acc1[p] = 0ULL; }

    #pragma unroll 8
    for (int h = 0; h < HN; ++h) {
        const int ih = __shfl_sync(0xffffffffu, idx, h);
        const float2 xv = *(const float2*)(x + (size_t)ih * CIN + 2 * lane);
        const unsigned long long x0 = pk2(xv.x, xv.x);
        const unsigned long long x1 = pk2(xv.y, xv.y);
        const ulonglong2* wsv = (const ulonglong2*)&ws4[warp][h][0];
        #pragma unroll
        for (int pp = 0; pp < 4; ++pp) {
            ulonglong2 wp = wsv[pp];
            acc0[2 * pp]     = ffma2(wp.x, x0, acc0[2 * pp]);
            acc1[2 * pp]     = ffma2(wp.x, x1, acc1[2 * pp]);
            acc0[2 * pp + 1] = ffma2(wp.y, x0, acc0[2 * pp + 1]);
            acc1[2 * pp + 1] = ffma2(wp.y, x1, acc1[2 * pp + 1]);
        }
    }

    __nv_bfloat16* wh = g_wth + (size_t)q * KTOT + 2 * lane;
    __nv_bfloat16* wl = g_wtl + (size_t)q * KTOT + 2 * lane;
    #pragma unroll
    for (int p = 0; p < 8; ++p) {
        float v00, v10, v01, v11;
        upk2(acc0[p], v00, v10);
        upk2(acc1[p], v01, v11);
        {
            const int k = 2 * p;
            __nv_bfloat16 h0 = __float2bfloat16(v00);
            __nv_bfloat16 h1 = __float2bfloat16(v01);
            __nv_bfloat16 l0 = __float2bfloat16(v00 - __bfloat162float(h0));
            __nv_bfloat16 l1 = __float2bfloat16(v01 - __bfloat162float(h1));
            *(__nv_bfloat162*)(wh + k * 64) = __nv_bfloat162(h0, h1);
            *(__nv_bfloat162*)(wl + k * 64) = __nv_bfloat162(l0, l1);
        }
        if (2 * p + 1 < KP) {
            const int k = 2 * p + 1;
            __nv_bfloat16 h0 = __float2bfloat16(v10);
            __nv_bfloat16 h1 = __float2bfloat16(v11);
            __nv_bfloat16 l0 = __float2bfloat16(v10 - __bfloat162float(h0));
            __nv_bfloat16 l1 = __float2bfloat16(v11 - __bfloat162float(h1));
            *(__nv_bfloat162*)(wh + k * 64) = __nv_bfloat162(h0, h1);
            *(__nv_bfloat162*)(wl + k * 64) = __nv_bfloat162(l0, l1);
        }
    }
}

// =============================================================================
// Kernel B: HMMA GEMM  out[128-tile][64] = weighted x W^T  (3-term bf16)
//   CTA 256 thr (8 warps), warp = 16 rows x 64 cols
//   SW128-swizzled SMEM, cp.async double buffer
// =============================================================================
// SMEM per buffer: A_hi 16KB, A_lo 16KB, W_hi 8KB, W_lo 8KB  -> 48KB; x2 = 96KB
#define HB_AH(b) ((b) * 49152u + 0u)
#define HB_AL(b) ((b) * 49152u + 16384u)
#define HB_WH(b) ((b) * 49152u + 32768u)
#define HB_WL(b) ((b) * 49152u + 40960u)
#define HB_TOTAL (98304)

extern __shared__ char smH[];

static __device__ __forceinline__ void load_chunk(uint32_t sb, int buf, int qbase, int c,
                                                  int tid) {
    // A hi/lo: 1024 16B units each
    #pragma unroll
    for (int i = 0; i < 4; ++i) {
        const int v = i * 256 + tid;
        const int row = v >> 3, u = v & 7;
        const uint32_t d = SWZ128((uint32_t)(row * 128 + u * 16));
        const size_t so = (size_t)(qbase + row) * KTOT + c * 64 + u * 8;
        cp_async16(sb + HB_AH(buf) + d, g_wth + so);
        cp_async16(sb + HB_AL(buf) + d, g_wtl + so);
    }
    // W hi/lo: 512 16B units each
    #pragma unroll
    for (int i = 0; i < 2; ++i) {
        const int v = i * 256 + tid;
        const int row = v >> 3, u = v & 7;
        const uint32_t d = SWZ128((uint32_t)(row * 128 + u * 16));
        const size_t so = (size_t)row * KTOT + c * 64 + u * 8;
        cp_async16(sb + HB_WH(buf) + d, g_Wth + so);
        cp_async16(sb + HB_WL(buf) + d, g_Wtl + so);
    }
    cp_commit();
}

__global__ void __launch_bounds__(256, 2)
kpconv_gemm_hmma(float* __restrict__ out)
{
    const uint32_t sb = smem_u32(smH);
    const int tid   = threadIdx.x;
    const int warp  = tid >> 5;
    const int lane  = tid & 31;
    const int qbase = blockIdx.x * 128;

    // ldmatrix lane address components
    const int a_row = warp * 16 + (lane & 15);
    const int a_cb  = (lane >> 4) * 16;                     // byte offset in 32B k-step
    const int b_row = (lane & 7) + ((lane >> 4) << 3);      // row within 16-row pair
    const int b_cb  = ((lane >> 3) & 1) * 16;

    float acc[8][4];
    #pragma unroll
    for (int t = 0; t < 8; ++t)
        #pragma unroll
        for (int e = 0; e < 4; ++e) acc[t][e] = 0.f;

    load_chunk(sb, 0, qbase, 0, tid);
    load_chunk(sb, 1, qbase, 1, tid);

    #pragma unroll 1
    for (int c = 0; c < 15; ++c) {
        const int buf = c & 1;
        if (c < 14) cp_wait1(); else cp_wait0();
        __syncthreads();

        const uint32_t ahb = sb + HB_AH(buf);
        const uint32_t alb = sb + HB_AL(buf);
        const uint32_t whb = sb + HB_WH(buf);
        const uint32_t wlb = sb + HB_WL(buf);

        #pragma unroll
        for (int s = 0; s < 4; ++s) {
            const uint32_t aoff = SWZ128((uint32_t)(a_row * 128 + s * 32 + a_cb));
            uint32_t ah0, ah1, ah2, ah3, al0, al1, al2, al3;
            LDSM4(ah0, ah1, ah2, ah3, ahb + aoff);
            LDSM4(al0, al1, al2, al3, alb + aoff);

            #pragma unroll
            for (int p = 0; p < 4; ++p) {
                const uint32_t boff =
                    SWZ128((uint32_t)((p * 16 + b_row) * 128 + s * 32 + b_cb));
                uint32_t bh0, bh1, bh2, bh3, bl0, bl1, bl2, bl3;
                LDSM4(bh0, bh1, bh2, bh3, whb + boff);
                LDSM4(bl0, bl1, bl2, bl3, wlb + boff);

                MMA16816(acc[2 * p],     ah0, ah1, ah2, ah3, bh0, bh1);
                MMA16816(acc[2 * p],     ah0, ah1, ah2, ah3, bl0, bl1);
                MMA16816(acc[2 * p],     al0, al1, al2, al3, bh0, bh1);
                MMA16816(acc[2 * p + 1], ah0, ah1, ah2, ah3, bh2, bh3);
                MMA16816(acc[2 * p + 1], ah0, ah1, ah2, ah3, bl2, bl3);
                MMA16816(acc[2 * p + 1], al0, al1, al2, al3, bh2, bh3);
            }
        }

        __syncthreads();                       // all reads of buf done
        if (c + 2 < 15) load_chunk(sb, buf, qbase, c + 2, tid);
    }

    // ---- epilogue: write 16x64 per warp ----
    const int tm = lane >> 2;                  // 0..7
    const int tn = (lane & 3) * 2;
    const int n0 = qbase + warp * 16 + tm;
    #pragma unroll
    for (int t = 0; t < 8; ++t) {
        const int col = t * 8 + tn;
        *(float2*)(out + (size_t)n0 * CO + col)       = make_float2(acc[t][0], acc[t][1]);
        *(float2*)(out + (size_t)(n0 + 8) * CO + col) = make_float2(acc[t][2], acc[t][3]);
    }
}

// =============================================================================
// Kernel S: BN partial sums over out
// =============================================================================
__global__ void __launch_bounds__(256)
bn_stats(const float* __restrict__ out) {
    __shared__ float r1[4][64], r2[4][64];
    const int c  = threadIdx.x & 63;
    const int rg = threadIdx.x >> 6;
    float s = 0.f, s2 = 0.f;
    for (int r = blockIdx.x * 4 + rg; r < NQ; r += 4096) {
        float v = out[(size_t)r * CO + c];
        s += v;
        s2 = fmaf(v, v, s2);
    }
    r1[rg][c] = s; r2[rg][c] = s2;
    __syncthreads();
    if (threadIdx.x < 64) {
        float a = 0.f, b = 0.f;
        #pragma unroll
        for (int g = 0; g < 4; ++g) { a += r1[g][threadIdx.x]; b += r2[g][threadIdx.x]; }
        atomicAdd(&g_sums[threadIdx.x], a);
        atomicAdd(&g_sumsq[threadIdx.x], b);
    }
}

// =============================================================================
__global__ void finalize_stats_kernel(const float* __restrict__ gamma,
                                      const float* __restrict__ beta) {
    int o = threadIdx.x;
    if (o < CO) {
        const float invN = 1.f / (float)NQ;
        float mean = g_sums[o] * invN;
        float var  = g_sumsq[o] * invN - mean * mean;
        float inv  = rsqrtf(var + 1e-5f);
        float sc   = gamma[o] * inv;
        g_scale[o] = sc;
        g_bias[o]  = fmaf(-mean, sc, beta[o]);
    }
}

__global__ void __launch_bounds__(256)
bn_act_kernel(float* __restrict__ out) {
    const int i = blockIdx.x * 256 + threadIdx.x;
    float4 v = ((const float4*)out)[i];
    const int c = (i & 15) * 4;
    float r0 = fmaf(v.x, g_scale[c + 0], g_bias[c + 0]);
    float r1 = fmaf(v.y, g_scale[c + 1], g_bias[c + 1]);
    float r2 = fmaf(v.z, g_scale[c + 2], g_bias[c + 2]);
    float r3 = fmaf(v.w, g_scale[c + 3], g_bias[c + 3]);
    r0 = (r0 >= 0.f) ? r0 : 0.1f * r0;
    r1 = (r1 >= 0.f) ? r1 : 0.1f * r1;
    r2 = (r2 >= 0.f) ? r2 : 0.1f * r2;
    r3 = (r3 >= 0.f) ? r3 : 0.1f * r3;
    ((float4*)out)[i] = make_float4(r0, r1, r2, r3);
}

// =============================================================================
extern "C" void kernel_launch(void* const* d_in, const int* in_sizes, int n_in,
                              void* d_out, int out_size) {
    const float* x      = (const float*)d_in[0];
    const float* q_pts  = (const float*)d_in[1];
    const float* s_pts  = (const float*)d_in[2];
    const int*   nbr    = (const int*)d_in[3];
    const float* kp     = (const float*)d_in[4];
    const float* Wg     = (const float*)d_in[5];
    const float* gamma  = (const float*)d_in[6];
    const float* beta   = (const float*)d_in[7];
    float*       out    = (float*)d_out;

    cudaFuncSetAttribute(kpconv_gemm_hmma,
                         cudaFuncAttributeMaxDynamicSharedMemorySize, HB_TOTAL);

    prep_w<<<KTOT, 64>>>(Wg);
    kpconv_aggregate<<<NQ / 8, 256>>>(x, q_pts, s_pts, nbr, kp);
    kpconv_gemm_hmma<<<NQ / 128, 256, HB_TOTAL>>>(out);
    bn_stats<<<1024, 256>>>(out);
    finalize_stats_kernel<<<1, 64>>>(gamma, beta);
    bn_act_kernel<<<(NQ * CO / 4) / 256, 256>>>(out);
}